// round 1
// baseline (speedup 1.0000x reference)
#include <cuda_runtime.h>
#include <cstdint>

#define N_NODES 100000
#define N_EDGES 1200000
#define D 64

// ---------------- device scratch (no allocation allowed) ----------------
__device__ float g_h[(size_t)N_NODES * D];    // H = (x @ W) * dinv[node]
__device__ float g_agg[(size_t)N_NODES * D];  // scatter accumulator
__device__ float g_t[(size_t)N_NODES * D];    // layer-1 output
__device__ float g_dinv[N_NODES];
__device__ int   g_deg[N_NODES];
__device__ int   g_src[N_EDGES];
__device__ int   g_dst[N_EDGES];
__device__ int   g_idx64;                     // 1 if edge_index is int64

// ---------------- index dtype detection ----------------
// int64 little-endian with values < 2^31  =>  int32 view is [lo, 0, lo, 0, ...]
// int32 random src values in [0,100000): P(128 consecutive odd words all 0) ~ 0
__global__ void detect_kernel(const int* __restrict__ raw) {
    if (threadIdx.x == 0 && blockIdx.x == 0) {
        int is64 = 1;
        #pragma unroll 1
        for (int i = 0; i < 128; i++) {
            if (raw[2 * i + 1] != 0) { is64 = 0; break; }
        }
        g_idx64 = is64;
    }
}

__global__ void zero_deg_kernel() {
    int i = blockIdx.x * blockDim.x + threadIdx.x;
    if (i < N_NODES) g_deg[i] = 0;
}

// normalize edge indices to int32 + count in-degree on dst
__global__ void convert_count_kernel(const void* __restrict__ eidx) {
    int e = blockIdx.x * blockDim.x + threadIdx.x;
    if (e >= N_EDGES) return;
    int s, d;
    if (g_idx64) {
        const long long* p = (const long long*)eidx;
        s = (int)p[e];
        d = (int)p[N_EDGES + e];
    } else {
        const int* p = (const int*)eidx;
        s = p[e];
        d = p[N_EDGES + e];
    }
    g_src[e] = s;
    g_dst[e] = d;
    atomicAdd(&g_deg[d], 1);
}

__global__ void dinv_kernel() {
    int i = blockIdx.x * blockDim.x + threadIdx.x;
    if (i < N_NODES) {
        // +1 for self loop; deg always > 0
        g_dinv[i] = rsqrtf((float)(g_deg[i] + 1));
    }
}

// ---------------- GEMM: H[i] = (X[i] @ W) * dinv[i]; AGG[i] = H[i] (self loop)
// 32 rows per block, 256 threads: 8 threads per row, 8 output cols per thread.
__global__ __launch_bounds__(256) void gemm_scale_kernel(
    const float* __restrict__ X, const float* __restrict__ W) {
    __shared__ float sW[64 * 64];
    __shared__ float sX[32 * 65];   // padded stride to kill bank conflicts

    int tid = threadIdx.x;
    #pragma unroll
    for (int i = tid; i < 64 * 64; i += 256) sW[i] = W[i];

    int row0 = blockIdx.x * 32;
    for (int i = tid; i < 32 * 64; i += 256) {
        int r = i >> 6, c = i & 63;
        int gr = row0 + r;
        sX[r * 65 + c] = (gr < N_NODES) ? X[(size_t)gr * D + c] : 0.0f;
    }
    __syncthreads();

    int r = tid >> 3;       // 0..31
    int t = tid & 7;        // 0..7
    int gr = row0 + r;
    if (gr >= N_NODES) return;

    float acc[8] = {0.f, 0.f, 0.f, 0.f, 0.f, 0.f, 0.f, 0.f};
    #pragma unroll
    for (int k = 0; k < 64; k++) {
        float xv = sX[r * 65 + k];
        #pragma unroll
        for (int c = 0; c < 8; c++)
            acc[c] += xv * sW[k * 64 + t * 8 + c];
    }

    float dv = g_dinv[gr];
    size_t base = (size_t)gr * D + t * 8;
    #pragma unroll
    for (int c = 0; c < 8; c++) {
        float v = acc[c] * dv;
        g_h[base + c]   = v;
        g_agg[base + c] = v;   // self-loop contribution initializes agg
    }
}

// ---------------- scatter: AGG[dst] += H[src], 16 threads/edge (float4 lanes)
__global__ __launch_bounds__(256) void scatter_kernel() {
    long long t = (long long)blockIdx.x * blockDim.x + threadIdx.x;
    long long edge = t >> 4;
    if (edge >= N_EDGES) return;
    int part = (int)(t & 15);

    int s = g_src[edge];
    int d = g_dst[edge];

    const float4* H4 = (const float4*)g_h;
    float4 v = H4[(size_t)s * 16 + part];

    float* a = g_agg + (size_t)d * D + part * 4;
    atomicAdd(a + 0, v.x);
    atomicAdd(a + 1, v.y);
    atomicAdd(a + 2, v.z);
    atomicAdd(a + 3, v.w);
}

// ---------------- epilogue: OUT = prelu(dinv[node]*AGG + b, a)
__global__ void epilogue_kernel(const float* __restrict__ b,
                                const float* __restrict__ a,
                                float* __restrict__ OUT) {
    int i = blockIdx.x * blockDim.x + threadIdx.x;
    if (i >= N_NODES * D) return;
    int node = i >> 6;
    int c = i & 63;
    float v = g_dinv[node] * g_agg[i] + b[c];
    OUT[i] = (v >= 0.0f) ? v : a[c] * v;
}

extern "C" void kernel_launch(void* const* d_in, const int* in_sizes, int n_in,
                              void* d_out, int out_size) {
    const float* x    = (const float*)d_in[0];
    const void*  eidx = d_in[1];
    const float* W1   = (const float*)d_in[2];
    const float* b1   = (const float*)d_in[3];
    const float* a1   = (const float*)d_in[4];
    const float* W2   = (const float*)d_in[5];
    const float* b2   = (const float*)d_in[6];
    const float* a2   = (const float*)d_in[7];
    float* out = (float*)d_out;

    float* d_h;   cudaGetSymbolAddress((void**)&d_h,  g_h);   // only for epilogue1 target
    float* d_t;   cudaGetSymbolAddress((void**)&d_t,  g_t);

    const int TB = 256;
    int nodeBlocks = (N_NODES + TB - 1) / TB;
    int edgeBlocks = (N_EDGES + TB - 1) / TB;
    int scatBlocks = (int)(((long long)N_EDGES * 16 + TB - 1) / TB);
    int elemBlocks = (N_NODES * D + TB - 1) / TB;
    int gemmBlocks = (N_NODES + 31) / 32;

    // --- graph preprocessing ---
    detect_kernel<<<1, 32>>>((const int*)eidx);
    zero_deg_kernel<<<nodeBlocks, TB>>>();
    convert_count_kernel<<<edgeBlocks, TB>>>(eidx);
    dinv_kernel<<<nodeBlocks, TB>>>();

    // --- layer 1 ---
    gemm_scale_kernel<<<gemmBlocks, TB>>>(x, W1);
    scatter_kernel<<<scatBlocks, TB>>>();
    epilogue_kernel<<<elemBlocks, TB>>>(b1, a1, d_t);

    // --- layer 2 ---
    gemm_scale_kernel<<<gemmBlocks, TB>>>(d_t, W2);
    scatter_kernel<<<scatBlocks, TB>>>();
    epilogue_kernel<<<elemBlocks, TB>>>(b2, a2, out);
}

// round 5
// speedup vs baseline: 1.9990x; 1.9990x over previous
#include <cuda_runtime.h>
#include <cstdint>

#define N_NODES 100000
#define N_EDGES 1200000
#define D 64

#define SCAN_BLK 1024
#define N_SCAN_BLKS ((N_NODES + SCAN_BLK - 1) / SCAN_BLK)   // 98

// ---------------- device scratch (no allocation allowed) ----------------
__device__ float g_h[(size_t)N_NODES * D];    // H = (x @ W) * dinv[node]
__device__ float g_t[(size_t)N_NODES * D];    // layer-1 output
__device__ float g_dinv[N_NODES];
__device__ int   g_deg[N_NODES];
__device__ int   g_off[N_NODES + 1];          // CSR row offsets (by dst)
__device__ int   g_cur[N_NODES];              // fill cursors
__device__ int   g_src[N_EDGES];
__device__ int   g_dst[N_EDGES];
__device__ int   g_csr[N_EDGES];              // src ids grouped by dst
__device__ int   g_bsum[N_SCAN_BLKS];
__device__ int   g_bsumscan[N_SCAN_BLKS];
__device__ int   g_idx64;                     // 1 if edge_index is int64

// ---------------- index dtype detection ----------------
// int64 little-endian with values < 2^31 => int32 view is [lo, 0, lo, 0, ...]
__global__ void detect_kernel(const int* __restrict__ raw) {
    if (threadIdx.x == 0 && blockIdx.x == 0) {
        int is64 = 1;
        #pragma unroll 1
        for (int i = 0; i < 128; i++) {
            if (raw[2 * i + 1] != 0) { is64 = 0; break; }
        }
        g_idx64 = is64;
    }
}

__global__ void zero_deg_kernel() {
    int i = blockIdx.x * blockDim.x + threadIdx.x;
    if (i < N_NODES) g_deg[i] = 0;
}

// normalize edge indices to int32 + count in-degree on dst
__global__ void convert_count_kernel(const void* __restrict__ eidx) {
    int e = blockIdx.x * blockDim.x + threadIdx.x;
    if (e >= N_EDGES) return;
    int s, d;
    if (g_idx64) {
        const long long* p = (const long long*)eidx;
        s = (int)p[e];
        d = (int)p[N_EDGES + e];
    } else {
        const int* p = (const int*)eidx;
        s = p[e];
        d = p[N_EDGES + e];
    }
    g_src[e] = s;
    g_dst[e] = d;
    atomicAdd(&g_deg[d], 1);
}

__global__ void dinv_kernel() {
    int i = blockIdx.x * blockDim.x + threadIdx.x;
    if (i < N_NODES) g_dinv[i] = rsqrtf((float)(g_deg[i] + 1));  // +1 self loop
}

// ---------------- exclusive scan of deg -> g_off ----------------
__global__ __launch_bounds__(SCAN_BLK) void scan_block_kernel() {
    __shared__ int sh[SCAN_BLK];
    int i = blockIdx.x * SCAN_BLK + threadIdx.x;
    int v = (i < N_NODES) ? g_deg[i] : 0;
    sh[threadIdx.x] = v;
    __syncthreads();
    #pragma unroll
    for (int off = 1; off < SCAN_BLK; off <<= 1) {
        int t = (threadIdx.x >= off) ? sh[threadIdx.x - off] : 0;
        __syncthreads();
        sh[threadIdx.x] += t;
        __syncthreads();
    }
    if (i < N_NODES) g_off[i + 1] = sh[threadIdx.x];       // per-block inclusive
    if (threadIdx.x == SCAN_BLK - 1) g_bsum[blockIdx.x] = sh[SCAN_BLK - 1];
}

__global__ void scan_sums_kernel() {   // 1 block, 128 threads (N_SCAN_BLKS<=128)
    __shared__ int sh[128];
    int v = (threadIdx.x < N_SCAN_BLKS) ? g_bsum[threadIdx.x] : 0;
    sh[threadIdx.x] = v;
    __syncthreads();
    #pragma unroll
    for (int off = 1; off < 128; off <<= 1) {
        int t = (threadIdx.x >= off) ? sh[threadIdx.x - off] : 0;
        __syncthreads();
        sh[threadIdx.x] += t;
        __syncthreads();
    }
    if (threadIdx.x < N_SCAN_BLKS) g_bsumscan[threadIdx.x] = sh[threadIdx.x];
}

__global__ __launch_bounds__(SCAN_BLK) void scan_add_kernel() {
    int i = blockIdx.x * SCAN_BLK + threadIdx.x;
    if (i < N_NODES) {
        int v = g_off[i + 1];
        if (blockIdx.x > 0) v += g_bsumscan[blockIdx.x - 1];
        g_off[i + 1] = v;
        g_cur[i] = v - g_deg[i];   // exclusive start = cursor init
    }
    if (i == 0) g_off[0] = 0;
}

// ---------------- fill CSR ----------------
__global__ void fill_kernel() {
    int e = blockIdx.x * blockDim.x + threadIdx.x;
    if (e >= N_EDGES) return;
    int d = g_dst[e];
    int pos = atomicAdd(&g_cur[d], 1);
    g_csr[pos] = g_src[e];
}

// ---------------- GEMM: H[i] = (X[i] @ W) * dinv[i] ----------------
// 32 rows/block, 256 threads: 8 threads per row, 8 output cols each.
__global__ __launch_bounds__(256) void gemm_scale_kernel(
    const float* __restrict__ X, const float* __restrict__ W) {
    __shared__ float sW[64 * 64];
    __shared__ float sX[32 * 65];

    int tid = threadIdx.x;
    #pragma unroll
    for (int i = tid; i < 64 * 64; i += 256) sW[i] = W[i];

    int row0 = blockIdx.x * 32;
    for (int i = tid; i < 32 * 64; i += 256) {
        int r = i >> 6, c = i & 63;
        int gr = row0 + r;
        sX[r * 65 + c] = (gr < N_NODES) ? X[(size_t)gr * D + c] : 0.0f;
    }
    __syncthreads();

    int r = tid >> 3;
    int t = tid & 7;
    int gr = row0 + r;
    if (gr >= N_NODES) return;

    float acc[8] = {0.f, 0.f, 0.f, 0.f, 0.f, 0.f, 0.f, 0.f};
    #pragma unroll
    for (int k = 0; k < 64; k++) {
        float xv = sX[r * 65 + k];
        #pragma unroll
        for (int c = 0; c < 8; c++)
            acc[c] += xv * sW[k * 64 + t * 8 + c];
    }

    float dv = g_dinv[gr];
    size_t base = (size_t)gr * D + t * 8;
    #pragma unroll
    for (int c = 0; c < 8; c++) g_h[base + c] = acc[c] * dv;
}

// ---------------- fused gather + norm + bias + PReLU ----------------
// One warp per destination node; lane holds float2 column slice.
__global__ __launch_bounds__(256) void gather_kernel(
    const float* __restrict__ b, const float* __restrict__ a,
    float* __restrict__ OUT) {
    int warp = (blockIdx.x * 256 + threadIdx.x) >> 5;
    int lane = threadIdx.x & 31;
    if (warp >= N_NODES) return;
    int d = warp;

    const float2* H2 = (const float2*)g_h;
    float2 acc = H2[(size_t)d * 32 + lane];       // self-loop term

    int e  = g_off[d];
    int e1 = g_off[d + 1];
    // software pipeline: keep a couple of loads in flight
    for (; e + 1 < e1; e += 2) {
        int s0 = g_csr[e];
        int s1 = g_csr[e + 1];
        float2 v0 = H2[(size_t)s0 * 32 + lane];
        float2 v1 = H2[(size_t)s1 * 32 + lane];
        acc.x += v0.x + v1.x;
        acc.y += v0.y + v1.y;
    }
    if (e < e1) {
        int s = g_csr[e];
        float2 v = H2[(size_t)s * 32 + lane];
        acc.x += v.x;
        acc.y += v.y;
    }

    float dv = g_dinv[d];
    float2 bb = ((const float2*)b)[lane];
    float2 aa = ((const float2*)a)[lane];
    float vx = dv * acc.x + bb.x;
    float vy = dv * acc.y + bb.y;
    float2 o;
    o.x = (vx >= 0.0f) ? vx : aa.x * vx;
    o.y = (vy >= 0.0f) ? vy : aa.y * vy;
    ((float2*)OUT)[(size_t)d * 32 + lane] = o;
}

extern "C" void kernel_launch(void* const* d_in, const int* in_sizes, int n_in,
                              void* d_out, int out_size) {
    const float* x    = (const float*)d_in[0];
    const void*  eidx = d_in[1];
    const float* W1   = (const float*)d_in[2];
    const float* b1   = (const float*)d_in[3];
    const float* a1   = (const float*)d_in[4];
    const float* W2   = (const float*)d_in[5];
    const float* b2   = (const float*)d_in[6];
    const float* a2   = (const float*)d_in[7];
    float* out = (float*)d_out;

    float* d_t;
    cudaGetSymbolAddress((void**)&d_t, g_t);

    const int TB = 256;
    int nodeBlocks  = (N_NODES + TB - 1) / TB;
    int edgeBlocks  = (N_EDGES + TB - 1) / TB;
    int gemmBlocks  = (N_NODES + 31) / 32;
    int gatherBlocks = (N_NODES * 32 + TB - 1) / TB;

    // --- graph preprocessing ---
    detect_kernel<<<1, 32>>>((const int*)eidx);
    zero_deg_kernel<<<nodeBlocks, TB>>>();
    convert_count_kernel<<<edgeBlocks, TB>>>(eidx);
    dinv_kernel<<<nodeBlocks, TB>>>();
    scan_block_kernel<<<N_SCAN_BLKS, SCAN_BLK>>>();
    scan_sums_kernel<<<1, 128>>>();
    scan_add_kernel<<<N_SCAN_BLKS, SCAN_BLK>>>();
    fill_kernel<<<edgeBlocks, TB>>>();

    // --- layer 1 ---
    gemm_scale_kernel<<<gemmBlocks, TB>>>(x, W1);
    gather_kernel<<<gatherBlocks, TB>>>(b1, a1, d_t);

    // --- layer 2 ---
    gemm_scale_kernel<<<gemmBlocks, TB>>>(d_t, W2);
    gather_kernel<<<gatherBlocks, TB>>>(b2, a2, out);
}